// round 15
// baseline (speedup 1.0000x reference)
#include <cuda_runtime.h>

#define B_TOK 32768
#define NB 16
#define KC 256
#define DD 64

// smem strides (floats), 16B-aligned rows
#define SC 264            // codebook row stride
#define SX 132            // x-tile row stride
// smem float offsets
#define S_CBT 0
#define S_XT  (S_CBT + DD * SC)          // 16896
#define S_C2  (S_XT + DD * SX)           // 25344
#define S_X2  (S_C2 + KC)                // 25600
#define S_RED (S_X2 + 128)               // 25728 (8B aligned: *4 % 8 == 0)
#define SMEM_FLOATS (S_RED + 128 * 16 * 2)   // 29824 floats = 119296 B

// output layout: concat of flattened returns, all f32
#define OFF_CODES 0
#define OFF_RECON (B_TOK * NB)                       // 524288
#define OFF_NCB   (OFF_RECON + B_TOK * NB * DD)      // 34078720
#define OFF_NC    (OFF_NCB + NB * KC * DD)           // 34340864
#define OFF_NW    (OFF_NC + NB * KC)                 // 34344960

// scratch (no allocation allowed -> device globals; zero-initialized at load,
// re-zeroed by k_ema every launch so graph replays are deterministic)
__device__ float g_counts[NB * KC];
__device__ float g_dw[NB * KC * DD];
__device__ int   g_codes[B_TOK * NB];

__device__ __forceinline__ void red_add_v4(float* addr, float a, float b, float c, float d) {
    asm volatile("red.global.add.v4.f32 [%0], {%1, %2, %3, %4};"
                 :: "l"(addr), "f"(a), "f"(b), "f"(c), "f"(d) : "memory");
}

__device__ __forceinline__ unsigned long long pack2(float lo, float hi) {
    unsigned long long r;
    asm("mov.b64 %0, {%1, %2};" : "=l"(r) : "f"(lo), "f"(hi));
    return r;
}

// ---------------------------------------------------------------------------
// k_assign: block = (book, 128-token tile). Register-tiled GEMM:
// 256 threads as 16 token-groups (ti) x 16 code-groups (tj); each thread
// accumulates 8 tokens x 16 codes (64 f32x2 accumulators) in ONE pass over d.
// Argmin: thread-local first-min over its 16 codes (ascending k), then 16-way
// smem reduction per token scanning tj ascending with strict <  ==> global
// first-index tie-break preserved (d2 values bitwise identical everywhere).
// Numerics (frozen, bitwise-matched to reference):
//   x2, c2 : sequential scalar chain d=0..63, UNFUSED mul+add
//   dot    : sequential fused fma chain d=0..63 (per f32x2 lane)
//   d2     : single-rounded (x2 - 2s) then + c2
//   argmin : ascending k, strict <  (first-index tie-break)
// ---------------------------------------------------------------------------
extern __shared__ float s_mem[];

__global__ __launch_bounds__(256, 1) void k_assign(
    const float* __restrict__ x,
    const float* __restrict__ cb,
    float* __restrict__ out)
{
    float* s_cbt = s_mem + S_CBT;   // [DD][SC]
    float* s_xt  = s_mem + S_XT;    // [DD][SX]
    float* s_c2  = s_mem + S_C2;    // [KC]
    float* s_x2  = s_mem + S_X2;    // [128]
    unsigned long long* s_red = (unsigned long long*)(s_mem + S_RED);  // [128][16]

    const int tid  = threadIdx.x;
    const int n    = blockIdx.x & (NB - 1);
    const int tile = blockIdx.x >> 4;       // 256 tiles of 128 tokens
    const int ti   = tid & 15;              // token group (8 tokens)
    const int tj   = tid >> 4;              // code group (16 codes)
    const int kbase = tj * 16;

    // ---- stage codebook transposed [d][k] (coalesced float4 reads) ----
    {
        const float4* src = (const float4*)(cb + n * KC * DD);
        #pragma unroll
        for (int t = 0; t < (KC * DD / 4) / 256; ++t) {
            int idx = tid + t * 256;
            float4 v = src[idx];
            int k  = idx >> 4;
            int d4 = (idx & 15) << 2;
            s_cbt[(d4 + 0) * SC + k] = v.x;
            s_cbt[(d4 + 1) * SC + k] = v.y;
            s_cbt[(d4 + 2) * SC + k] = v.z;
            s_cbt[(d4 + 3) * SC + k] = v.w;
        }
    }
    // ---- stage x tile transposed [d][tok] (coalesced float4 reads) ----
    {
        #pragma unroll
        for (int t = 0; t < (128 * DD / 4) / 256; ++t) {
            int idx = tid + t * 256;
            int tok = idx >> 4;
            int d4  = (idx & 15) << 2;
            float4 v = *(const float4*)(x + (long)(tile * 128 + tok) * (NB * DD) + n * DD + d4);
            s_xt[(d4 + 0) * SX + tok] = v.x;
            s_xt[(d4 + 1) * SX + tok] = v.y;
            s_xt[(d4 + 2) * SX + tok] = v.z;
            s_xt[(d4 + 3) * SX + tok] = v.w;
        }
    }
    __syncthreads();

    // ---- c2[k=tid]: sequential UNFUSED chain over d (bitwise-frozen order) ----
    {
        float acc = 0.f;
        #pragma unroll
        for (int d = 0; d < DD; ++d) {
            float c = s_cbt[d * SC + tid];
            acc = __fadd_rn(acc, __fmul_rn(c, c));
        }
        s_c2[tid] = acc;
    }
    // ---- x2[tok=tid<128]: sequential UNFUSED chain (bitwise-frozen order) ----
    if (tid < 128) {
        float acc = 0.f;
        #pragma unroll
        for (int d = 0; d < DD; ++d) {
            float v = s_xt[d * SX + tid];
            acc = __fadd_rn(acc, __fmul_rn(v, v));
        }
        s_x2[tid] = acc;
    }
    __syncthreads();

    // ---- main GEMM: acc[t][p] = sum_d x[t][d] * cpair[p][d] (fused, seq d) ----
    unsigned long long acc[64];
    #pragma unroll
    for (int i = 0; i < 64; ++i) acc[i] = 0ull;

    #pragma unroll 2
    for (int d = 0; d < DD; ++d) {
        const float* xrow = &s_xt[d * SX + ti * 8];
        const float* crow = &s_cbt[d * SC + kbase];
        float4 tA = *(const float4*)(xrow);
        float4 tB = *(const float4*)(xrow + 4);
        ulonglong2 cp0 = *(const ulonglong2*)(crow);
        ulonglong2 cp1 = *(const ulonglong2*)(crow + 4);
        ulonglong2 cp2 = *(const ulonglong2*)(crow + 8);
        ulonglong2 cp3 = *(const ulonglong2*)(crow + 12);
        unsigned long long cp[8] = {cp0.x, cp0.y, cp1.x, cp1.y, cp2.x, cp2.y, cp3.x, cp3.y};
        float xt[8] = {tA.x, tA.y, tA.z, tA.w, tB.x, tB.y, tB.z, tB.w};
        #pragma unroll
        for (int t = 0; t < 8; ++t) {
            unsigned long long xx;
            asm("mov.b64 %0, {%1, %1};" : "=l"(xx) : "f"(xt[t]));
            #pragma unroll
            for (int p = 0; p < 8; ++p)
                asm("fma.rn.f32x2 %0, %1, %2, %0;" : "+l"(acc[t * 8 + p]) : "l"(xx), "l"(cp[p]));
        }
    }

    // ---- epilogue: d2 assembly + thread-local first-min over 16 codes ----
    const unsigned long long NEG2 = pack2(-2.0f, -2.0f);
    unsigned long long c2p[8];
    #pragma unroll
    for (int p = 0; p < 8; ++p) c2p[p] = *(const unsigned long long*)&s_c2[kbase + 2 * p];

    #pragma unroll
    for (int t = 0; t < 8; ++t) {
        const int tok = ti * 8 + t;
        float x2v = s_x2[tok];
        unsigned long long X2P = pack2(x2v, x2v);
        float best = 3.402823466e38f;
        int bi = kbase;
        #pragma unroll
        for (int p = 0; p < 8; ++p) {
            unsigned long long e;
            float flo, fhi;
            asm("fma.rn.f32x2 %0, %1, %2, %3;" : "=l"(e) : "l"(acc[t * 8 + p]), "l"(NEG2), "l"(X2P));
            asm("add.rn.f32x2 %0, %0, %1;" : "+l"(e) : "l"(c2p[p]));
            asm("mov.b64 {%0, %1}, %2;" : "=f"(flo), "=f"(fhi) : "l"(e));
            if (flo < best) { best = flo; bi = kbase + 2 * p; }
            if (fhi < best) { best = fhi; bi = kbase + 2 * p + 1; }
        }
        // d2 > 0 always here (||x-c||^2 ~ 60), so float-bit ordering == value ordering
        s_red[tok * 16 + tj] = ((unsigned long long)__float_as_uint(best) << 32) | (unsigned)bi;
    }
    __syncthreads();

    // ---- final reduce (one thread per token, tj ascending => k ascending) ----
    if (tid < 128) {
        const int tok = tid;
        unsigned long long bestkey = s_red[tok * 16 + 0];
        #pragma unroll
        for (int j = 1; j < 16; ++j) {
            unsigned long long key = s_red[tok * 16 + j];
            if (key < bestkey) bestkey = key;
        }
        const int bi = (int)(bestkey & 0xFFFFFFFFu);
        const int b  = tile * 128 + tok;

        g_codes[b * NB + n] = bi;
        out[OFF_CODES + b * NB + n] = (float)bi;
        atomicAdd(&g_counts[n * KC + bi], 1.0f);

        float* dwp = &g_dw[(n * KC + bi) * DD];
        #pragma unroll
        for (int i = 0; i < DD / 4; ++i) {
            float v0 = s_xt[(4 * i + 0) * SX + tok];
            float v1 = s_xt[(4 * i + 1) * SX + tok];
            float v2 = s_xt[(4 * i + 2) * SX + tok];
            float v3 = s_xt[(4 * i + 3) * SX + tok];
            red_add_v4(dwp + 4 * i, v0, v1, v2, v3);
        }
    }
}

// ---------------------------------------------------------------------------
// k_ema: new_count / new_weight / new_codebooks (float4), and re-zero scratch
// for the next graph replay (read-then-zero; counts staged across a barrier).
// ---------------------------------------------------------------------------
__global__ void k_ema(const float* __restrict__ ema_count,
                      const float* __restrict__ ema_weight,
                      float* __restrict__ out)
{
    int i4 = blockIdx.x * 256 + threadIdx.x;   // 65536 float4 slots
    int nk = i4 >> 4;
    float cnt = g_counts[nk];
    __syncthreads();                            // all reads of g_counts before zeroing
    if ((i4 & 15) == 0) g_counts[nk] = 0.f;

    float nc = __fadd_rn(__fmul_rn(0.99f, ema_count[nk]), __fmul_rn(0.01f, cnt));
    float ncp = __fadd_rn(nc, 1e-5f);

    float4 w  = *(const float4*)&ema_weight[i4 * 4];
    float4 dw = *(float4*)&g_dw[i4 * 4];
    *(float4*)&g_dw[i4 * 4] = make_float4(0.f, 0.f, 0.f, 0.f);

    float4 nw, ncb;
    nw.x = __fadd_rn(__fmul_rn(0.99f, w.x), __fmul_rn(0.01f, dw.x));
    nw.y = __fadd_rn(__fmul_rn(0.99f, w.y), __fmul_rn(0.01f, dw.y));
    nw.z = __fadd_rn(__fmul_rn(0.99f, w.z), __fmul_rn(0.01f, dw.z));
    nw.w = __fadd_rn(__fmul_rn(0.99f, w.w), __fmul_rn(0.01f, dw.w));
    ncb.x = __fdiv_rn(nw.x, ncp);
    ncb.y = __fdiv_rn(nw.y, ncp);
    ncb.z = __fdiv_rn(nw.z, ncp);
    ncb.w = __fdiv_rn(nw.w, ncp);

    *(float4*)&out[OFF_NW + i4 * 4]  = nw;
    *(float4*)&out[OFF_NCB + i4 * 4] = ncb;
    if ((i4 & 15) == 0) out[OFF_NC + nk] = nc;
}

// ---------------------------------------------------------------------------
// k_recon: gather new_codebooks[n, codes[b,n], :] as float4
// ---------------------------------------------------------------------------
__global__ void k_recon(float* __restrict__ out)
{
    int i4 = blockIdx.x * 256 + threadIdx.x;   // 8.39M float4 slots
    int b  = i4 >> 8;                          // 256 float4 per token
    int j  = i4 & 255;
    int n  = j >> 4;
    int d4 = j & 15;
    int code = g_codes[b * NB + n];
    float4 v = *(const float4*)&out[OFF_NCB + (n * KC + code) * DD + d4 * 4];
    *(float4*)&out[OFF_RECON + i4 * 4] = v;
}

// ---------------------------------------------------------------------------
extern "C" void kernel_launch(void* const* d_in, const int* in_sizes, int n_in,
                              void* d_out, int out_size)
{
    const float* x          = (const float*)d_in[0];
    const float* codebooks  = (const float*)d_in[1];
    const float* ema_count  = (const float*)d_in[2];
    const float* ema_weight = (const float*)d_in[3];
    float* out = (float*)d_out;

    const int smem_bytes = SMEM_FLOATS * sizeof(float);   // 119296
    cudaFuncSetAttribute(k_assign, cudaFuncAttributeMaxDynamicSharedMemorySize, smem_bytes);

    const int n_blocks = (B_TOK / 128) * NB;              // 4096
    k_assign<<<n_blocks, 256, smem_bytes>>>(x, codebooks, out);
    k_ema<<<(NB * KC * DD / 4) / 256, 256>>>(ema_count, ema_weight, out);
    k_recon<<<(B_TOK * NB * DD / 4) / 256, 256>>>(out);
}